// round 1
// baseline (speedup 1.0000x reference)
#include <cuda_runtime.h>
#include <cuda_bf16.h>
#include <cstdint>

#define B_ROWS 4096
#define M_ROWS 12893
#define M_PAD  12928   // 101 * 128
#define D_DIM  2048

#define BM 128
#define BN 128
#define BK 32
#define PAD 8
#define LDA (BK + PAD)     // 40 bf16 = 80 bytes row stride (16B aligned)
#define NK (D_DIM / BK)    // 64

// Scratch (device globals: allocation-free rule)
__device__ __nv_bfloat16 g_xn[B_ROWS * D_DIM];
__device__ __nv_bfloat16 g_pn[(size_t)M_PAD * D_DIM];
__device__ float g_xs[B_ROWS];
__device__ float g_ps[M_PAD];

__device__ __forceinline__ void cp_async16(void* sp, const void* gp) {
    uint32_t sa = (uint32_t)__cvta_generic_to_shared(sp);
    asm volatile("cp.async.cg.shared.global [%0], [%1], 16;" :: "r"(sa), "l"(gp));
}

__device__ __forceinline__ float block_reduce_sum(float v, float* red) {
    #pragma unroll
    for (int o = 16; o > 0; o >>= 1) v += __shfl_xor_sync(0xffffffffu, v, o);
    int w = threadIdx.x >> 5;
    if ((threadIdx.x & 31) == 0) red[w] = v;
    __syncthreads();
    if (threadIdx.x < 32) {
        float t = (threadIdx.x < 8) ? red[threadIdx.x] : 0.f;
        #pragma unroll
        for (int o = 4; o > 0; o >>= 1) t += __shfl_xor_sync(0xffffffffu, t, o);
        if (threadIdx.x == 0) red[0] = t;
    }
    __syncthreads();
    float r = red[0];
    __syncthreads();   // red reused by second call
    return r;
}

// which==0: x -> g_xn/g_xs ; which==1: prototypes -> g_pn/g_ps
__global__ void __launch_bounds__(256) normalize_rows(const float* __restrict__ in,
                                                      int rows_valid, int which) {
    __shared__ float red[8];
    const int row = blockIdx.x;
    const int tid = threadIdx.x;
    __nv_bfloat16* out = which ? g_pn : g_xn;
    float* sq = which ? g_ps : g_xs;

    if (row >= rows_valid) {
        // zero padded prototype rows so the GEMM mainloop needs no guards
        __nv_bfloat16 z = __float2bfloat16(0.f);
        for (int i = tid; i < D_DIM; i += 256) out[(size_t)row * D_DIM + i] = z;
        if (tid == 0) sq[row] = 0.f;
        return;
    }

    const float4* rp = (const float4*)(in + (size_t)row * D_DIM);
    float4 v0 = rp[tid];
    float4 v1 = rp[tid + 256];
    float s = v0.x * v0.x + v0.y * v0.y + v0.z * v0.z + v0.w * v0.w
            + v1.x * v1.x + v1.y * v1.y + v1.z * v1.z + v1.w * v1.w;
    float tot = block_reduce_sum(s, red);
    float inv = 1.f / fmaxf(sqrtf(tot), 1e-12f);

    float n0x = v0.x * inv, n0y = v0.y * inv, n0z = v0.z * inv, n0w = v0.w * inv;
    float n1x = v1.x * inv, n1y = v1.y * inv, n1z = v1.z * inv, n1w = v1.w * inv;
    float ss = n0x * n0x + n0y * n0y + n0z * n0z + n0w * n0w
             + n1x * n1x + n1y * n1y + n1z * n1z + n1w * n1w;

    __nv_bfloat162* o2 = (__nv_bfloat162*)(out + (size_t)row * D_DIM);
    int b0 = tid * 2;            // bf162 index for first float4 (floats tid*4..tid*4+3)
    int b1 = 512 + tid * 2;      // second float4 (floats 1024+tid*4 ..)
    o2[b0]     = __floats2bfloat162_rn(n0x, n0y);
    o2[b0 + 1] = __floats2bfloat162_rn(n0z, n0w);
    o2[b1]     = __floats2bfloat162_rn(n1x, n1y);
    o2[b1 + 1] = __floats2bfloat162_rn(n1z, n1w);

    float stot = block_reduce_sum(ss, red);
    if (tid == 0) sq[row] = stot;
}

__global__ void __launch_bounds__(256, 2) gemm_dist_kernel(const float* __restrict__ dscale,
                                                           float* __restrict__ out) {
    __shared__ __nv_bfloat16 sA[2][BM * LDA];
    __shared__ __nv_bfloat16 sB[2][BN * LDA];

    const int tid  = threadIdx.x;
    const int warp = tid >> 5;
    const int lane = tid & 31;
    const int wm = warp >> 1;       // 0..3 -> 32-row strips
    const int wn = warp & 1;        // 0..1 -> 64-col strips
    const int bm = blockIdx.y * BM; // always < 4096, exact
    const int bn = blockIdx.x * BN; // covers M_PAD exactly

    float acc[2][8][4];
    #pragma unroll
    for (int i = 0; i < 2; i++)
        #pragma unroll
        for (int j = 0; j < 8; j++)
            #pragma unroll
            for (int t = 0; t < 4; t++) acc[i][j][t] = 0.f;

    auto loadTile = [&](int buf, int kt) {
        int k0 = kt * BK;
        #pragma unroll
        for (int h = 0; h < 2; h++) {
            int c = tid + h * 256;      // 512 16B-chunks per operand tile
            int row = c >> 2, q = c & 3;
            cp_async16(&sA[buf][row * LDA + q * 8],
                       g_xn + (size_t)(bm + row) * D_DIM + k0 + q * 8);
            cp_async16(&sB[buf][row * LDA + q * 8],
                       g_pn + (size_t)(bn + row) * D_DIM + k0 + q * 8);
        }
        asm volatile("cp.async.commit_group;");
    };

    loadTile(0, 0);
    int buf = 0;
    for (int kt = 0; kt < NK; kt++) {
        asm volatile("cp.async.wait_group 0;");
        __syncthreads();
        if (kt + 1 < NK) loadTile(buf ^ 1, kt + 1);

        #pragma unroll
        for (int ks = 0; ks < 2; ks++) {
            const int kk = ks * 16;
            const int kq = kk + (lane & 3) * 2;
            uint32_t bfr[8][2];
            #pragma unroll
            for (int j = 0; j < 8; j++) {
                int n = wn * 64 + j * 8 + (lane >> 2);
                bfr[j][0] = *(const uint32_t*)&sB[buf][n * LDA + kq];
                bfr[j][1] = *(const uint32_t*)&sB[buf][n * LDA + kq + 8];
            }
            #pragma unroll
            for (int i = 0; i < 2; i++) {
                int r = wm * 32 + i * 16 + (lane >> 2);
                uint32_t a0 = *(const uint32_t*)&sA[buf][r * LDA + kq];
                uint32_t a1 = *(const uint32_t*)&sA[buf][(r + 8) * LDA + kq];
                uint32_t a2 = *(const uint32_t*)&sA[buf][r * LDA + kq + 8];
                uint32_t a3 = *(const uint32_t*)&sA[buf][(r + 8) * LDA + kq + 8];
                #pragma unroll
                for (int j = 0; j < 8; j++) {
                    asm volatile(
                        "mma.sync.aligned.m16n8k16.row.col.f32.bf16.bf16.f32 "
                        "{%0,%1,%2,%3}, {%4,%5,%6,%7}, {%8,%9}, {%0,%1,%2,%3};"
                        : "+f"(acc[i][j][0]), "+f"(acc[i][j][1]),
                          "+f"(acc[i][j][2]), "+f"(acc[i][j][3])
                        : "r"(a0), "r"(a1), "r"(a2), "r"(a3),
                          "r"(bfr[j][0]), "r"(bfr[j][1]));
                }
            }
        }
        buf ^= 1;
    }

    const float absS = fabsf(dscale[0]);
    #pragma unroll
    for (int i = 0; i < 2; i++) {
        int r = bm + wm * 32 + i * 16 + (lane >> 2);
        float xs0 = g_xs[r];
        float xs1 = g_xs[r + 8];
        #pragma unroll
        for (int j = 0; j < 8; j++) {
            int c = bn + wn * 64 + j * 8 + (lane & 3) * 2;
            #pragma unroll
            for (int t = 0; t < 2; t++) {
                int cc = c + t;
                if (cc < M_ROWS) {
                    float pv = g_ps[cc];
                    float d2a = xs0 + pv - 2.f * acc[i][j][t];
                    out[(size_t)r * M_ROWS + cc] =
                        -absS * sqrtf(fmaxf(d2a, 0.f));
                    float d2b = xs1 + pv - 2.f * acc[i][j][2 + t];
                    out[(size_t)(r + 8) * M_ROWS + cc] =
                        -absS * sqrtf(fmaxf(d2b, 0.f));
                }
            }
        }
    }
}

extern "C" void kernel_launch(void* const* d_in, const int* in_sizes, int n_in,
                              void* d_out, int out_size) {
    const float* x  = (const float*)d_in[0];   // [4096, 2048]
    const float* pr = (const float*)d_in[1];   // [12893, 2048]
    const float* sc = (const float*)d_in[2];   // [1]
    float* out = (float*)d_out;                // [4096, 12893]

    normalize_rows<<<B_ROWS, 256>>>(x, B_ROWS, 0);
    normalize_rows<<<M_PAD, 256>>>(pr, M_ROWS, 1);

    dim3 grid(M_PAD / BN, B_ROWS / BM);        // 101 x 32
    gemm_dist_kernel<<<grid, 256>>>(sc, out);
}

// round 4
// speedup vs baseline: 1.3378x; 1.3378x over previous
#include <cuda_runtime.h>
#include <cuda_bf16.h>
#include <cstdint>

#define B_ROWS 4096
#define M_ROWS 12893
#define M_PAD  13056          // 51 * 256
#define D_DIM  2048

#define BM 128                // CTA rows
#define BN 256                // CTA cols
#define BK 64                 // k-chunk: 64 bf16 = 128B = one swizzle row
#define NK (D_DIM / BK)       // 32
#define STAGES 3
#define A_BYTES (BM * 128)    // 16384
#define B_BYTES (BN * 128)    // 32768
#define B_OFF_S A_BYTES
#define STAGE_BYTES (A_BYTES + B_BYTES)       // 49152
#define SMEM_DYN (STAGES * STAGE_BYTES)       // 147456

// ---------------- device scratch (allocation-free rule) ----------------
__device__ __nv_bfloat16 g_xn[B_ROWS * D_DIM];
__device__ __nv_bfloat16 g_pn[(size_t)M_PAD * D_DIM];
__device__ float g_xs[B_ROWS];
__device__ float g_ps[M_PAD];

__device__ __forceinline__ void cp_async16(uint32_t sa, const void* gp) {
    asm volatile("cp.async.cg.shared.global [%0], [%1], 16;" :: "r"(sa), "l"(gp));
}
__device__ __forceinline__ void ldsm_x4(uint32_t& r0, uint32_t& r1,
                                        uint32_t& r2, uint32_t& r3, uint32_t a) {
    asm volatile("ldmatrix.sync.aligned.m8n8.x4.shared.b16 {%0,%1,%2,%3}, [%4];"
                 : "=r"(r0), "=r"(r1), "=r"(r2), "=r"(r3) : "r"(a));
}

// ---------------- normalize ----------------
__device__ __forceinline__ float block_reduce_sum(float v, float* red) {
    #pragma unroll
    for (int o = 16; o > 0; o >>= 1) v += __shfl_xor_sync(0xffffffffu, v, o);
    int w = threadIdx.x >> 5;
    if ((threadIdx.x & 31) == 0) red[w] = v;
    __syncthreads();
    if (threadIdx.x < 32) {
        float t = (threadIdx.x < 8) ? red[threadIdx.x] : 0.f;
        #pragma unroll
        for (int o = 4; o > 0; o >>= 1) t += __shfl_xor_sync(0xffffffffu, t, o);
        if (threadIdx.x == 0) red[0] = t;
    }
    __syncthreads();
    float r = red[0];
    __syncthreads();
    return r;
}

__global__ void __launch_bounds__(256) normalize_rows(const float* __restrict__ in,
                                                      int rows_valid, int which) {
    __shared__ float red[8];
    const int row = blockIdx.x;
    const int tid = threadIdx.x;
    __nv_bfloat16* out = which ? g_pn : g_xn;
    float* sq = which ? g_ps : g_xs;

    if (row >= rows_valid) {
        __nv_bfloat16 z = __float2bfloat16(0.f);
        for (int i = tid; i < D_DIM; i += 256) out[(size_t)row * D_DIM + i] = z;
        if (tid == 0) sq[row] = 0.f;
        return;
    }
    const float4* rp = (const float4*)(in + (size_t)row * D_DIM);
    float4 v0 = rp[tid];
    float4 v1 = rp[tid + 256];
    float s = v0.x * v0.x + v0.y * v0.y + v0.z * v0.z + v0.w * v0.w
            + v1.x * v1.x + v1.y * v1.y + v1.z * v1.z + v1.w * v1.w;
    float tot = block_reduce_sum(s, red);
    float inv = 1.f / fmaxf(sqrtf(tot), 1e-12f);

    float n0x = v0.x * inv, n0y = v0.y * inv, n0z = v0.z * inv, n0w = v0.w * inv;
    float n1x = v1.x * inv, n1y = v1.y * inv, n1z = v1.z * inv, n1w = v1.w * inv;
    float ss = n0x * n0x + n0y * n0y + n0z * n0z + n0w * n0w
             + n1x * n1x + n1y * n1y + n1z * n1z + n1w * n1w;

    __nv_bfloat162* o2 = (__nv_bfloat162*)(out + (size_t)row * D_DIM);
    int b0 = tid * 2, b1 = 512 + tid * 2;
    o2[b0]     = __floats2bfloat162_rn(n0x, n0y);
    o2[b0 + 1] = __floats2bfloat162_rn(n0z, n0w);
    o2[b1]     = __floats2bfloat162_rn(n1x, n1y);
    o2[b1 + 1] = __floats2bfloat162_rn(n1z, n1w);

    float stot = block_reduce_sum(ss, red);
    if (tid == 0) sq[row] = stot;
}

// ---------------- mma.sync GEMM + fused distance epilogue ----------------
__global__ void __launch_bounds__(512, 1) gemm_dist_mma(const float* __restrict__ dscale,
                                                        float* __restrict__ out) {
    extern __shared__ __align__(1024) char smem[];
    const uint32_t sbase = (uint32_t)__cvta_generic_to_shared(smem);

    const int tid  = threadIdx.x;
    const int lane = tid & 31;
    const int warp = tid >> 5;
    const int wm = warp >> 2;      // 0..3: 32-row strip
    const int wn = warp & 3;       // 0..3: 64-col strip
    const int bm0 = blockIdx.y * BM;
    const int bn  = blockIdx.x * BN;

    // ---- ldmatrix lane address precompute (SW128: swz(r*128+cb)=r*128+(cb^((r&7)*16)))
    const int a_row = (lane & 7) + ((lane >> 3) & 1) * 8;  // 0..15
    const int a_kh  = lane >> 4;                            // k half
    const int b_row = (lane & 7) + (lane >> 4) * 8;         // n local 0..15
    const int b_kh  = (lane >> 3) & 1;
    const uint32_t xm = (lane & 7) * 16;

    uint32_t aoff[2], boff[4];
    #pragma unroll
    for (int i = 0; i < 2; i++) aoff[i] = (wm * 32 + i * 16 + a_row) * 128;
    #pragma unroll
    for (int jb = 0; jb < 4; jb++)
        boff[jb] = B_OFF_S + (wn * 64 + jb * 16 + b_row) * 128;

    float acc[2][8][4];
    #pragma unroll
    for (int i = 0; i < 2; i++)
        #pragma unroll
        for (int j = 0; j < 8; j++)
            #pragma unroll
            for (int t = 0; t < 4; t++) acc[i][j][t] = 0.f;

    auto loadStage = [&](int st, int kt) {
        const int k0 = kt * BK;
        const uint32_t base = sbase + st * STAGE_BYTES;
        #pragma unroll
        for (int h = 0; h < 2; h++) {               // A: 1024 16B chunks
            int c = tid + h * 512;
            int row = c >> 3, q = c & 7;
            cp_async16(base + row * 128 + ((q * 16) ^ ((row & 7) * 16)),
                       g_xn + (size_t)(bm0 + row) * D_DIM + k0 + q * 8);
        }
        #pragma unroll
        for (int h = 0; h < 4; h++) {               // B: 2048 16B chunks
            int c = tid + h * 512;
            int row = c >> 3, q = c & 7;
            cp_async16(base + B_OFF_S + row * 128 + ((q * 16) ^ ((row & 7) * 16)),
                       g_pn + (size_t)(bn + row) * D_DIM + k0 + q * 8);
        }
    };

    loadStage(0, 0);
    asm volatile("cp.async.commit_group;" ::: "memory");
    loadStage(1, 1);
    asm volatile("cp.async.commit_group;" ::: "memory");

    for (int kt = 0; kt < NK; kt++) {
        asm volatile("cp.async.wait_group 1;" ::: "memory");
        __syncthreads();

        if (kt + 2 < NK) loadStage((kt + 2) % STAGES, kt + 2);
        asm volatile("cp.async.commit_group;" ::: "memory");

        const uint32_t base = sbase + (kt % STAGES) * STAGE_BYTES;
        #pragma unroll
        for (int ks = 0; ks < 4; ks++) {
            const uint32_t ca = ((uint32_t)(ks * 32 + a_kh * 16)) ^ xm;
            const uint32_t cb = ((uint32_t)(ks * 32 + b_kh * 16)) ^ xm;
            uint32_t A[2][4];
            #pragma unroll
            for (int i = 0; i < 2; i++)
                ldsm_x4(A[i][0], A[i][1], A[i][2], A[i][3], base + aoff[i] + ca);
            uint32_t Bf[8][2];
            #pragma unroll
            for (int jb = 0; jb < 4; jb++) {
                uint32_t r0, r1, r2, r3;
                ldsm_x4(r0, r1, r2, r3, base + boff[jb] + cb);
                Bf[2 * jb][0] = r0; Bf[2 * jb][1] = r1;
                Bf[2 * jb + 1][0] = r2; Bf[2 * jb + 1][1] = r3;
            }
            #pragma unroll
            for (int i = 0; i < 2; i++)
                #pragma unroll
                for (int j = 0; j < 8; j++) {
                    asm volatile(
                        "mma.sync.aligned.m16n8k16.row.col.f32.bf16.bf16.f32 "
                        "{%0,%1,%2,%3}, {%4,%5,%6,%7}, {%8,%9}, {%0,%1,%2,%3};"
                        : "+f"(acc[i][j][0]), "+f"(acc[i][j][1]),
                          "+f"(acc[i][j][2]), "+f"(acc[i][j][3])
                        : "r"(A[i][0]), "r"(A[i][1]), "r"(A[i][2]), "r"(A[i][3]),
                          "r"(Bf[j][0]), "r"(Bf[j][1]));
                }
        }
    }

    // ---- fused epilogue: -|s| * sqrt(max(xs + ps - 2*acc, 0))
    const float absS = fabsf(dscale[0]);
    #pragma unroll
    for (int i = 0; i < 2; i++) {
        const int r = bm0 + wm * 32 + i * 16 + (lane >> 2);
        const float xs0 = g_xs[r];
        const float xs1 = g_xs[r + 8];
        #pragma unroll
        for (int j = 0; j < 8; j++) {
            const int c = bn + wn * 64 + j * 8 + (lane & 3) * 2;
            const float ps0 = __ldg(&g_ps[c]);
            const float ps1 = __ldg(&g_ps[c + 1]);
            float v00 = -absS * sqrtf(fmaxf(xs0 + ps0 - 2.f * acc[i][j][0], 0.f));
            float v01 = -absS * sqrtf(fmaxf(xs0 + ps1 - 2.f * acc[i][j][1], 0.f));
            float v10 = -absS * sqrtf(fmaxf(xs1 + ps0 - 2.f * acc[i][j][2], 0.f));
            float v11 = -absS * sqrtf(fmaxf(xs1 + ps1 - 2.f * acc[i][j][3], 0.f));
            if (c + 1 < M_ROWS) {
                out[(size_t)r * M_ROWS + c] = v00;
                out[(size_t)r * M_ROWS + c + 1] = v01;
                out[(size_t)(r + 8) * M_ROWS + c] = v10;
                out[(size_t)(r + 8) * M_ROWS + c + 1] = v11;
            } else if (c < M_ROWS) {
                out[(size_t)r * M_ROWS + c] = v00;
                out[(size_t)(r + 8) * M_ROWS + c] = v10;
            }
        }
    }
}

extern "C" void kernel_launch(void* const* d_in, const int* in_sizes, int n_in,
                              void* d_out, int out_size) {
    const float* x  = (const float*)d_in[0];   // [4096, 2048]
    const float* pr = (const float*)d_in[1];   // [12893, 2048]
    const float* sc = (const float*)d_in[2];   // [1]
    float* out = (float*)d_out;                // [4096, 12893]

    cudaFuncSetAttribute(gemm_dist_mma,
                         cudaFuncAttributeMaxDynamicSharedMemorySize, SMEM_DYN);

    normalize_rows<<<B_ROWS, 256>>>(x, B_ROWS, 0);
    normalize_rows<<<M_PAD, 256>>>(pr, M_ROWS, 1);

    dim3 grid(M_PAD / BN, B_ROWS / BM);        // 51 x 32
    gemm_dist_mma<<<grid, 512, SMEM_DYN>>>(sc, out);
}